// round 13
// baseline (speedup 1.0000x reference)
#include <cuda_runtime.h>
#include <cuda_fp16.h>
#include <cstdint>

// ============================================================================
// CommNet via mma.sync m16n8k16 fp16 (compute_100-safe).
// 1 batch per CTA (M=64), grid=1024, 512 threads = 16 warps tiled 2(m) x 8(n).
// 2 CTAs/SM. h state in SMEM as hi/lo fp16x2 split pairs; MMAs consume hi only.
// Round-13 (pure layout round, math identical to round 12):
//   * B packs relaid [s][wn][lane][jn] -> 2x LDG.128 per s (was 4x LDG.64).
//   * G0 relaid [cta][slotgrp][tid] float4 -> 8x LDG/STG.128 (was 32 scalar).
//   * Tv A-tile: zero-row fragments (ah[1], ah[3]) passed as constants.
//   * Wd pack -> 1x LDG.128 per s; b2 via LDG.64.
// G0 = h0 @ W1c computed once (step 0), parked in gmem, re-added steps 1-3.
// ============================================================================

#define HID    256
#define MAG    64
#define STEPS  4
#define INVF   (1.0f/63.0f)
#define PITCH  72              // uint32 pitch of sHi/sLo[pair][*] (conflict-free)
#define SVP    24              // uint32 pitch of sSvA[kpair][row]

// SMEM byte offsets
#define SHI_OFF   0            // 128*72*4 = 36864
#define SLO_OFF   36864
#define SSVA_OFF  73728        // 128*24*4 = 12288 (Sv A-tile, rows 0/1 live)
#define SSVF_OFF  86016        // float[256] raw Sv accumulator
#define STV_OFF   87040        // float[256] Tv
#define SMEM_BYTES 88064

// ---------------- device scratch ----------------
// B-frag pack, layout: [(s*8+wn)*128 + lane*4 + jn] uint2 each.
// g: 0=W1eff 1=W1c 2=W2 3=inv*W1b
__device__ uint2 gPk2[4][16384];
__device__ uint2 gWdPk[1024];               // Wd^T: [s*64 + lane*2 + u]
__device__ float gG0[1024 * 32 * 512];      // [cta][slotgrp4][tid] float4-able

// ---------------- fp16 split helpers ----------------
__device__ __forceinline__ uint2 split2(float x0, float x1) {
    __half2 h = __float22half2_rn(make_float2(x0, x1));    // .x=low=x0
    float2 hf = __half22float2(h);
    __half2 l = __float22half2_rn(make_float2(x0 - hf.x, x1 - hf.y));
    uint2 r;
    r.x = *reinterpret_cast<uint32_t*>(&h);
    r.y = *reinterpret_cast<uint32_t*>(&l);
    return r;
}
__device__ __forceinline__ uint32_t f16x2_single(float x0, float x1) {
    __half2 h = __float22half2_rn(make_float2(x0, x1));
    return *reinterpret_cast<uint32_t*>(&h);
}
__device__ __forceinline__ float2 unsplit(uint32_t hx, uint32_t lx) {
    float2 fh = __half22float2(*reinterpret_cast<__half2*>(&hx));
    float2 fl = __half22float2(*reinterpret_cast<__half2*>(&lx));
    return make_float2(fh.x + fl.x, fh.y + fl.y);
}

#define MMA(c, a, B0, B1)                                                      \
    asm volatile("mma.sync.aligned.m16n8k16.row.col.f32.f16.f16.f32 "          \
                 "{%0,%1,%2,%3},{%4,%5,%6,%7},{%8,%9},{%0,%1,%2,%3};"          \
                 : "+f"((c)[0]), "+f"((c)[1]), "+f"((c)[2]), "+f"((c)[3])      \
                 : "r"((a)[0]), "r"((a)[1]), "r"((a)[2]), "r"((a)[3]),         \
                   "r"(B0), "r"(B1));

// ---------------- prep kernel ----------------
__global__ void prep_all(const float* __restrict__ W1, const float* __restrict__ W2,
                         const float* __restrict__ Wd) {
    int bid = blockIdx.x;
    if (bid < 256) {
        int idx = bid * 256 + threadIdx.x;     // 4 * 16384
        int gm = idx >> 14;
        int r  = idx & 16383;
        int s  = r >> 10;
        int u  = (r >> 5) & 31;
        int l  = r & 31;
        int g  = l >> 2, t = l & 3;
        int n  = u * 8 + g;
        int kb = s * 16 + 2 * t;
        int ks[4] = { kb, kb + 1, kb + 8, kb + 9 };
        float v[4];
        #pragma unroll
        for (int q = 0; q < 4; ++q) {
            int k = ks[q];
            if (gm == 0)      v[q] = W1[k * HID + n] - INVF * W1[(HID + k) * HID + n];
            else if (gm == 1) v[q] = W1[(2 * HID + k) * HID + n];
            else if (gm == 2) v[q] = W2[k * HID + n];
            else              v[q] = INVF * W1[(HID + k) * HID + n];
        }
        // jn-contiguous layout: [(s*8 + wn)*128 + lane*4 + jn]
        int wn_ = u >> 2, jn_ = u & 3;
        int nidx = (s * 8 + wn_) * 128 + l * 4 + jn_;
        gPk2[gm][nidx] = make_uint2(f16x2_single(v[0], v[1]), f16x2_single(v[2], v[3]));
    } else if (bid == 256) {
        for (int e = threadIdx.x; e < 1024; e += 256) {
            int l = e & 31;
            int u = (e >> 5) & 1;
            int s = e >> 6;
            int g = l >> 2, t = l & 3;
            int n = u * 8 + g;
            int kb = s * 16 + 2 * t;
            int ks[4] = { kb, kb + 1, kb + 8, kb + 9 };
            float v[4];
            #pragma unroll
            for (int q = 0; q < 4; ++q) v[q] = Wd[ks[q] * 16 + n];
            gWdPk[s * 64 + l * 2 + u] =
                make_uint2(f16x2_single(v[0], v[1]), f16x2_single(v[2], v[3]));
        }
    }
}

// ---------------- GEMM pass: acc += Ahi @ B --------------------------------
__device__ __forceinline__ void gemm_pass(const uint2* __restrict__ bp,
                                          float (&acc)[2][4][4],
                                          const uint32_t* __restrict__ sHi,
                                          int wm, int wn, int lane, int g, int t) {
    const uint4* bq = reinterpret_cast<const uint4*>(bp) + wn * 64 + lane * 2;
    const int mbase = wm * 32 + g;
    #pragma unroll 2
    for (int s = 0; s < 16; ++s) {
        uint4 q0 = __ldg(bq + s * 512);        // jn 0,1
        uint4 q1 = __ldg(bq + s * 512 + 1);    // jn 2,3
        const int kp0 = (s * 8 + t) * PITCH + mbase;
        const int kp2 = kp0 + 4 * PITCH;
        #pragma unroll
        for (int mt = 0; mt < 2; ++mt) {
            const int m0 = mt * 16;
            uint32_t ah[4];
            ah[0] = sHi[kp0 + m0]; ah[1] = sHi[kp0 + m0 + 8];
            ah[2] = sHi[kp2 + m0]; ah[3] = sHi[kp2 + m0 + 8];
            MMA(acc[mt][0], ah, q0.x, q0.y);
            MMA(acc[mt][1], ah, q0.z, q0.w);
            MMA(acc[mt][2], ah, q1.x, q1.y);
            MMA(acc[mt][3], ah, q1.z, q1.w);
        }
    }
}

// ---------------- main kernel ----------------
__global__ void __launch_bounds__(512, 2) commnet_mma_kernel(
    const int*   __restrict__ ids,
    const float* __restrict__ b1,
    const float* __restrict__ b2,
    const float* __restrict__ bd,
    const float* __restrict__ emb,
    float*       __restrict__ out)
{
    extern __shared__ uint8_t smraw[];
    uint32_t* sHi  = reinterpret_cast<uint32_t*>(smraw + SHI_OFF);   // [128][72]
    uint32_t* sLo  = reinterpret_cast<uint32_t*>(smraw + SLO_OFF);   // [128][72]
    uint32_t* sSvA = reinterpret_cast<uint32_t*>(smraw + SSVA_OFF);  // [128][24]
    float*    sSvF = reinterpret_cast<float*>(smraw + SSVF_OFF);     // [256]
    float*    sTv  = reinterpret_cast<float*>(smraw + STV_OFF);      // [256]

    const int cta  = blockIdx.x;
    const int tid  = threadIdx.x;
    const int w    = tid >> 5;
    const int lane = tid & 31;
    const int g    = lane >> 2;
    const int t    = lane & 3;
    const int wm   = w >> 3;              // m-half: rows [32wm, 32wm+32)
    const int wn   = w & 7;               // n-slice of 32

    // ---- zero Sv A-tile (rows 2-15 stay zero forever) ----
    for (int i = tid; i < 128 * SVP; i += 512) sSvA[i] = 0u;

    // ---- gather: h0 -> split pairs ----
    {
        int r  = tid >> 3;            // row 0..63
        int qt = tid & 7;             // column eighth
        int aid = ids[cta * MAG + r];
        const float4* er = reinterpret_cast<const float4*>(emb + aid * HID);
        #pragma unroll
        for (int q = 0; q < 8; ++q) {
            int f = qt * 8 + q;       // float4 index 0..63
            float4 e = er[f];
            int pair = 2 * f;
            uint2 pa = split2(e.x, e.y);
            uint2 pb = split2(e.z, e.w);
            sHi[pair * PITCH + r]       = pa.x; sLo[pair * PITCH + r]       = pa.y;
            sHi[(pair + 1) * PITCH + r] = pb.x; sLo[(pair + 1) * PITCH + r] = pb.y;
        }
    }

    float4* gp4 = reinterpret_cast<float4*>(gG0) + (size_t)cta * 4096 + tid;

    for (int step = 0; step < STEPS; ++step) {
        __syncthreads();

        if (step == 0) {
            // ---- initial Sv from smem (full read, step 0 only) ----
            #pragma unroll
            for (int pi = 0; pi < 8; ++pi) {
                int p = w * 8 + pi;
                float2 v0 = unsplit(sHi[p * PITCH + lane],      sLo[p * PITCH + lane]);
                float2 v1 = unsplit(sHi[p * PITCH + lane + 32], sLo[p * PITCH + lane + 32]);
                float se = v0.x + v1.x, so = v0.y + v1.y;
                #pragma unroll
                for (int off = 16; off; off >>= 1) {
                    se += __shfl_xor_sync(0xFFFFFFFFu, se, off);
                    so += __shfl_xor_sync(0xFFFFFFFFu, so, off);
                }
                if (lane == 0) { sSvF[2 * p] = se; sSvF[2 * p + 1] = so; }
            }
            __syncthreads();
        }

        // ---- build Sv A-tile rows 0 (hi) / 1 (lo) ----
        if (tid < 128) {
            float2 sv = *reinterpret_cast<const float2*>(sSvF + 2 * tid);
            uint2 pa = split2(sv.x, sv.y);
            sSvA[tid * SVP + 0] = pa.x;    // row 0: hi
            sSvA[tid * SVP + 1] = pa.y;    // row 1: lo
        }
        __syncthreads();

        // ---- Tv via MMA: Tv = b1 + (Sv_hi + Sv_lo) @ (inv*W1b) ----
        {
            float accT[2][4];
            #pragma unroll
            for (int jl = 0; jl < 2; ++jl)
                #pragma unroll
                for (int q = 0; q < 4; ++q) accT[jl][q] = 0.f;
            const int u0 = wn * 4 + wm * 2;
            // jn-contiguous pack: frag pair (jn=2wm, 2wm+1) = one uint4
            const uint4* bq = reinterpret_cast<const uint4*>(gPk2[3])
                              + wn * 64 + lane * 2 + wm;
            #pragma unroll 4
            for (int s = 0; s < 16; ++s) {
                uint4 q = __ldg(bq + s * 512);
                const int kp0 = (s * 8 + t) * SVP;
                uint32_t ah[4];
                ah[0] = sSvA[kp0 + g];           ah[1] = 0u;   // rows 8-15 zero
                ah[2] = sSvA[kp0 + 4 * SVP + g]; ah[3] = 0u;
                MMA(accT[0], ah, q.x, q.y);
                MMA(accT[1], ah, q.z, q.w);
            }
            #pragma unroll
            for (int jl = 0; jl < 2; ++jl) {
                int n0 = (u0 + jl) * 8 + 2 * t;
                float d0 = accT[jl][0], d1 = accT[jl][1];
                float r0 = __shfl_down_sync(0xFFFFFFFFu, d0, 4);   // row 1 (lo)
                float r1 = __shfl_down_sync(0xFFFFFFFFu, d1, 4);
                if (g == 0) {
                    float2 bb = *reinterpret_cast<const float2*>(b1 + n0);
                    reinterpret_cast<float2*>(sTv)[n0 >> 1] =
                        make_float2(d0 + r0 + bb.x, d1 + r1 + bb.y);
                }
            }
        }

        // ---- GEMM1 ----
        float acc[2][4][4];
        if (step == 0) {
            #pragma unroll
            for (int mt = 0; mt < 2; ++mt)
                #pragma unroll
                for (int jn = 0; jn < 4; ++jn)
                    #pragma unroll
                    for (int q = 0; q < 4; ++q) acc[mt][jn][q] = 0.f;
            gemm_pass(gPk2[1], acc, sHi, wm, wn, lane, g, t);       // G0 = h0@W1c
            #pragma unroll
            for (int mt = 0; mt < 2; ++mt)
                #pragma unroll
                for (int jn = 0; jn < 4; ++jn)
                    gp4[(mt * 4 + jn) * 512] = make_float4(acc[mt][jn][0], acc[mt][jn][1],
                                                           acc[mt][jn][2], acc[mt][jn][3]);
        } else {
            #pragma unroll
            for (int mt = 0; mt < 2; ++mt)
                #pragma unroll
                for (int jn = 0; jn < 4; ++jn) {
                    float4 v = gp4[(mt * 4 + jn) * 512];
                    acc[mt][jn][0] = v.x; acc[mt][jn][1] = v.y;
                    acc[mt][jn][2] = v.z; acc[mt][jn][3] = v.w;
                }
        }
        gemm_pass(gPk2[0], acc, sHi, wm, wn, lane, g, t);           // += h@W1eff
        __syncthreads();

        // ---- epilogue1: act = relu(acc+Tv) -> s* ; acc = h_old + b2 ----
        if (tid < 128)     // zero raw-Sv accumulator for the NEXT step
            reinterpret_cast<float2*>(sSvF)[tid] = make_float2(0.f, 0.f);
        #pragma unroll
        for (int mt = 0; mt < 2; ++mt) {
            const int m0 = wm * 32 + mt * 16 + g;
            #pragma unroll
            for (int jn = 0; jn < 4; ++jn) {
                const int pair = 16 * wn + 4 * jn + t;
                const int n0   = 32 * wn + 8 * jn + 2 * t;
                const int i0 = pair * PITCH + m0;
                float2 hoa = unsplit(sHi[i0],     sLo[i0]);
                float2 hob = unsplit(sHi[i0 + 8], sLo[i0 + 8]);
                float2 tv = *reinterpret_cast<const float2*>(sTv + n0);
                float a0 = fmaxf(acc[mt][jn][0] + tv.x, 0.f);
                float a1 = fmaxf(acc[mt][jn][1] + tv.y, 0.f);
                float a2 = fmaxf(acc[mt][jn][2] + tv.x, 0.f);
                float a3 = fmaxf(acc[mt][jn][3] + tv.y, 0.f);
                uint2 pa = split2(a0, a1);
                uint2 pb = split2(a2, a3);
                sHi[i0] = pa.x;     sLo[i0] = pa.y;
                sHi[i0 + 8] = pb.x; sLo[i0 + 8] = pb.y;
                float2 bb = *reinterpret_cast<const float2*>(b2 + n0);
                acc[mt][jn][0] = hoa.x + bb.x; acc[mt][jn][1] = hoa.y + bb.y;
                acc[mt][jn][2] = hob.x + bb.x; acc[mt][jn][3] = hob.y + bb.y;
            }
        }
        __syncthreads();

        // ---- GEMM2: acc += act @ W2   (acc = new h) ----
        gemm_pass(gPk2[2], acc, sHi, wm, wn, lane, g, t);
        __syncthreads();

        // ---- epilogue2: split new h -> s*; accumulate next Sv ----
        #pragma unroll
        for (int mt = 0; mt < 2; ++mt) {
            const int m0 = wm * 32 + mt * 16 + g;
            #pragma unroll
            for (int jn = 0; jn < 4; ++jn) {
                const int i0 = (16 * wn + 4 * jn + t) * PITCH + m0;
                uint2 pa = split2(acc[mt][jn][0], acc[mt][jn][1]);
                uint2 pb = split2(acc[mt][jn][2], acc[mt][jn][3]);
                sHi[i0] = pa.x;     sLo[i0] = pa.y;
                sHi[i0 + 8] = pb.x; sLo[i0 + 8] = pb.y;
            }
        }
        #pragma unroll
        for (int jn = 0; jn < 4; ++jn) {
            float s0 = acc[0][jn][0] + acc[0][jn][2] + acc[1][jn][0] + acc[1][jn][2];
            float s1 = acc[0][jn][1] + acc[0][jn][3] + acc[1][jn][1] + acc[1][jn][3];
            #pragma unroll
            for (int off = 4; off <= 16; off <<= 1) {      // sum over g (lane bits 2-4)
                s0 += __shfl_xor_sync(0xFFFFFFFFu, s0, off);
                s1 += __shfl_xor_sync(0xFFFFFFFFu, s1, off);
            }
            if (g == 0) {
                int n0 = 32 * wn + 8 * jn + 2 * t;
                atomicAdd(&sSvF[n0],     s0);
                atomicAdd(&sSvF[n0 + 1], s1);
            }
        }
    }

    __syncthreads();
    // ---- logits via MMA on warps wn==0: out = h @ Wd + bd  (hi+lo terms) ----
    if (wn == 0) {
        float accL[2][2][4];
        #pragma unroll
        for (int mt = 0; mt < 2; ++mt)
            #pragma unroll
            for (int jl = 0; jl < 2; ++jl) {
                int n0 = 8 * jl + 2 * t;
                float2 bv = *reinterpret_cast<const float2*>(bd + n0);
                accL[mt][jl][0] = bv.x; accL[mt][jl][1] = bv.y;
                accL[mt][jl][2] = bv.x; accL[mt][jl][3] = bv.y;
            }
        const int mbase = wm * 32 + g;
        const uint4* wq = reinterpret_cast<const uint4*>(gWdPk) + lane;
        #pragma unroll 4
        for (int s = 0; s < 16; ++s) {
            uint4 q = __ldg(wq + s * 32);      // {u=0 frag, u=1 frag}
            const int kp0 = (s * 8 + t) * PITCH + mbase;
            const int kp2 = kp0 + 4 * PITCH;
            #pragma unroll
            for (int mt = 0; mt < 2; ++mt) {
                const int m0 = mt * 16;
                uint32_t ah[4], al[4];
                ah[0] = sHi[kp0 + m0]; ah[1] = sHi[kp0 + m0 + 8];
                ah[2] = sHi[kp2 + m0]; ah[3] = sHi[kp2 + m0 + 8];
                al[0] = sLo[kp0 + m0]; al[1] = sLo[kp0 + m0 + 8];
                al[2] = sLo[kp2 + m0]; al[3] = sLo[kp2 + m0 + 8];
                MMA(accL[mt][0], ah, q.x, q.y);
                MMA(accL[mt][0], al, q.x, q.y);
                MMA(accL[mt][1], ah, q.z, q.w);
                MMA(accL[mt][1], al, q.z, q.w);
            }
        }
        #pragma unroll
        for (int mt = 0; mt < 2; ++mt) {
            const int m0 = wm * 32 + mt * 16 + g;
            #pragma unroll
            for (int jl = 0; jl < 2; ++jl) {
                const int n0 = 8 * jl + 2 * t;
                *reinterpret_cast<float2*>(out + (cta * MAG + m0) * 16 + n0) =
                    make_float2(accL[mt][jl][0], accL[mt][jl][1]);
                *reinterpret_cast<float2*>(out + (cta * MAG + m0 + 8) * 16 + n0) =
                    make_float2(accL[mt][jl][2], accL[mt][jl][3]);
            }
        }
    }
}

extern "C" void kernel_launch(void* const* d_in, const int* in_sizes, int n_in,
                              void* d_out, int out_size)
{
    const int*   ids = (const int*)  d_in[0];
    const float* emb = (const float*)d_in[1];
    const float* W1  = (const float*)d_in[2];
    const float* b1  = (const float*)d_in[3];
    const float* W2  = (const float*)d_in[4];
    const float* b2  = (const float*)d_in[5];
    const float* Wd  = (const float*)d_in[6];
    const float* bd  = (const float*)d_in[7];
    float* out = (float*)d_out;

    const int nCTA = in_sizes[0] / MAG;       // 1024

    prep_all<<<257, 256>>>(W1, W2, Wd);

    cudaFuncSetAttribute(commnet_mma_kernel,
                         cudaFuncAttributeMaxDynamicSharedMemorySize, SMEM_BYTES);
    commnet_mma_kernel<<<nCTA, 512, SMEM_BYTES>>>(ids, b1, b2, bd, emb, out);
}

// round 14
// speedup vs baseline: 1.1877x; 1.1877x over previous
#include <cuda_runtime.h>
#include <cuda_fp16.h>
#include <cstdint>

// ============================================================================
// CommNet via mma.sync m16n8k16 fp16 (compute_100-safe).
// 1 batch per CTA (M=64), grid=1024, 512 threads = 16 warps tiled 2(m) x 8(n).
// 2 CTAs/SM. h state in SMEM as hi/lo fp16x2 split pairs; MMAs consume hi only.
// Round-14: fixes round-13's stride-32B lane pattern. B pack is now
// LANE-CONTIGUOUS uint4 tiles: slot (s*8+wn)*64 + pair*32 + lane, pair=jn>>1,
// so each LDG.128 is one coalesced 512B warp transaction (round-12 wavefronts,
// half the instructions). Tv pack likewise (wn*64 + wm*32 + lane).
// G0 float4 + Wd packs already lane-contiguous (kept from round 13).
// G0 = h0 @ W1c computed once (step 0), parked in gmem, re-added steps 1-3.
// ============================================================================

#define HID    256
#define MAG    64
#define STEPS  4
#define INVF   (1.0f/63.0f)
#define PITCH  72              // uint32 pitch of sHi/sLo[pair][*] (conflict-free)
#define SVP    24              // uint32 pitch of sSvA[kpair][row]

// SMEM byte offsets
#define SHI_OFF   0            // 128*72*4 = 36864
#define SLO_OFF   36864
#define SSVA_OFF  73728        // 128*24*4 = 12288 (Sv A-tile, rows 0/1 live)
#define SSVF_OFF  86016        // float[256] raw Sv accumulator
#define STV_OFF   87040        // float[256] Tv
#define SMEM_BYTES 88064

// ---------------- device scratch ----------------
// B-frag pack, uint2 units; uint4 slot layout: (s*8+wn)*64 + (jn>>1)*32 + lane,
// slot = {frag jn=2p, frag jn=2p+1}.  g: 0=W1eff 1=W1c 2=W2 3=inv*W1b
__device__ uint2 gPk2[4][16384];
__device__ uint2 gWdPk[1024];               // Wd^T: uint4 slot s*32+lane = {u0,u1}
__device__ float gG0[1024 * 32 * 512];      // [cta][slotgrp4][tid] float4-able

// ---------------- fp16 split helpers ----------------
__device__ __forceinline__ uint2 split2(float x0, float x1) {
    __half2 h = __float22half2_rn(make_float2(x0, x1));    // .x=low=x0
    float2 hf = __half22float2(h);
    __half2 l = __float22half2_rn(make_float2(x0 - hf.x, x1 - hf.y));
    uint2 r;
    r.x = *reinterpret_cast<uint32_t*>(&h);
    r.y = *reinterpret_cast<uint32_t*>(&l);
    return r;
}
__device__ __forceinline__ uint32_t f16x2_single(float x0, float x1) {
    __half2 h = __float22half2_rn(make_float2(x0, x1));
    return *reinterpret_cast<uint32_t*>(&h);
}
__device__ __forceinline__ float2 unsplit(uint32_t hx, uint32_t lx) {
    float2 fh = __half22float2(*reinterpret_cast<__half2*>(&hx));
    float2 fl = __half22float2(*reinterpret_cast<__half2*>(&lx));
    return make_float2(fh.x + fl.x, fh.y + fl.y);
}

#define MMA(c, a, B0, B1)                                                      \
    asm volatile("mma.sync.aligned.m16n8k16.row.col.f32.f16.f16.f32 "          \
                 "{%0,%1,%2,%3},{%4,%5,%6,%7},{%8,%9},{%0,%1,%2,%3};"          \
                 : "+f"((c)[0]), "+f"((c)[1]), "+f"((c)[2]), "+f"((c)[3])      \
                 : "r"((a)[0]), "r"((a)[1]), "r"((a)[2]), "r"((a)[3]),         \
                   "r"(B0), "r"(B1));

// ---------------- prep kernel ----------------
__global__ void prep_all(const float* __restrict__ W1, const float* __restrict__ W2,
                         const float* __restrict__ Wd) {
    int bid = blockIdx.x;
    if (bid < 256) {
        int idx = bid * 256 + threadIdx.x;     // 4 * 16384
        int gm = idx >> 14;
        int r  = idx & 16383;
        int s  = r >> 10;
        int u  = (r >> 5) & 31;
        int l  = r & 31;
        int g  = l >> 2, t = l & 3;
        int n  = u * 8 + g;
        int kb = s * 16 + 2 * t;
        int ks[4] = { kb, kb + 1, kb + 8, kb + 9 };
        float v[4];
        #pragma unroll
        for (int q = 0; q < 4; ++q) {
            int k = ks[q];
            if (gm == 0)      v[q] = W1[k * HID + n] - INVF * W1[(HID + k) * HID + n];
            else if (gm == 1) v[q] = W1[(2 * HID + k) * HID + n];
            else if (gm == 2) v[q] = W2[k * HID + n];
            else              v[q] = INVF * W1[(HID + k) * HID + n];
        }
        // lane-contiguous uint4 tiles: uint2 index =
        //   ((s*8 + wn)*64 + (jn>>1)*32 + lane)*2 + (jn&1)
        int wn_ = u >> 2, jn_ = u & 3;
        int nidx = (((s * 8 + wn_) * 64 + (jn_ >> 1) * 32 + l) << 1) + (jn_ & 1);
        gPk2[gm][nidx] = make_uint2(f16x2_single(v[0], v[1]), f16x2_single(v[2], v[3]));
    } else if (bid == 256) {
        for (int e = threadIdx.x; e < 1024; e += 256) {
            int l = e & 31;
            int u = (e >> 5) & 1;
            int s = e >> 6;
            int g = l >> 2, t = l & 3;
            int n = u * 8 + g;
            int kb = s * 16 + 2 * t;
            int ks[4] = { kb, kb + 1, kb + 8, kb + 9 };
            float v[4];
            #pragma unroll
            for (int q = 0; q < 4; ++q) v[q] = Wd[ks[q] * 16 + n];
            gWdPk[s * 64 + l * 2 + u] =
                make_uint2(f16x2_single(v[0], v[1]), f16x2_single(v[2], v[3]));
        }
    }
}

// ---------------- GEMM pass: acc += Ahi @ B --------------------------------
__device__ __forceinline__ void gemm_pass(const uint2* __restrict__ bp,
                                          float (&acc)[2][4][4],
                                          const uint32_t* __restrict__ sHi,
                                          int wm, int wn, int lane, int g, int t) {
    const uint4* bq = reinterpret_cast<const uint4*>(bp) + wn * 64 + lane;
    const int mbase = wm * 32 + g;
    #pragma unroll 2
    for (int s = 0; s < 16; ++s) {
        uint4 q0 = __ldg(bq + s * 512);        // jn 0,1 (coalesced 512B)
        uint4 q1 = __ldg(bq + s * 512 + 32);   // jn 2,3 (coalesced 512B)
        const int kp0 = (s * 8 + t) * PITCH + mbase;
        const int kp2 = kp0 + 4 * PITCH;
        #pragma unroll
        for (int mt = 0; mt < 2; ++mt) {
            const int m0 = mt * 16;
            uint32_t ah[4];
            ah[0] = sHi[kp0 + m0]; ah[1] = sHi[kp0 + m0 + 8];
            ah[2] = sHi[kp2 + m0]; ah[3] = sHi[kp2 + m0 + 8];
            MMA(acc[mt][0], ah, q0.x, q0.y);
            MMA(acc[mt][1], ah, q0.z, q0.w);
            MMA(acc[mt][2], ah, q1.x, q1.y);
            MMA(acc[mt][3], ah, q1.z, q1.w);
        }
    }
}

// ---------------- main kernel ----------------
__global__ void __launch_bounds__(512, 2) commnet_mma_kernel(
    const int*   __restrict__ ids,
    const float* __restrict__ b1,
    const float* __restrict__ b2,
    const float* __restrict__ bd,
    const float* __restrict__ emb,
    float*       __restrict__ out)
{
    extern __shared__ uint8_t smraw[];
    uint32_t* sHi  = reinterpret_cast<uint32_t*>(smraw + SHI_OFF);   // [128][72]
    uint32_t* sLo  = reinterpret_cast<uint32_t*>(smraw + SLO_OFF);   // [128][72]
    uint32_t* sSvA = reinterpret_cast<uint32_t*>(smraw + SSVA_OFF);  // [128][24]
    float*    sSvF = reinterpret_cast<float*>(smraw + SSVF_OFF);     // [256]
    float*    sTv  = reinterpret_cast<float*>(smraw + STV_OFF);      // [256]

    const int cta  = blockIdx.x;
    const int tid  = threadIdx.x;
    const int w    = tid >> 5;
    const int lane = tid & 31;
    const int g    = lane >> 2;
    const int t    = lane & 3;
    const int wm   = w >> 3;              // m-half: rows [32wm, 32wm+32)
    const int wn   = w & 7;               // n-slice of 32

    // ---- zero Sv A-tile (rows 2-15 stay zero forever) ----
    for (int i = tid; i < 128 * SVP; i += 512) sSvA[i] = 0u;

    // ---- gather: h0 -> split pairs ----
    {
        int r  = tid >> 3;            // row 0..63
        int qt = tid & 7;             // column eighth
        int aid = ids[cta * MAG + r];
        const float4* er = reinterpret_cast<const float4*>(emb + aid * HID);
        #pragma unroll
        for (int q = 0; q < 8; ++q) {
            int f = qt * 8 + q;       // float4 index 0..63
            float4 e = er[f];
            int pair = 2 * f;
            uint2 pa = split2(e.x, e.y);
            uint2 pb = split2(e.z, e.w);
            sHi[pair * PITCH + r]       = pa.x; sLo[pair * PITCH + r]       = pa.y;
            sHi[(pair + 1) * PITCH + r] = pb.x; sLo[(pair + 1) * PITCH + r] = pb.y;
        }
    }

    float4* gp4 = reinterpret_cast<float4*>(gG0) + (size_t)cta * 4096 + tid;

    for (int step = 0; step < STEPS; ++step) {
        __syncthreads();

        if (step == 0) {
            // ---- initial Sv from smem (full read, step 0 only) ----
            #pragma unroll
            for (int pi = 0; pi < 8; ++pi) {
                int p = w * 8 + pi;
                float2 v0 = unsplit(sHi[p * PITCH + lane],      sLo[p * PITCH + lane]);
                float2 v1 = unsplit(sHi[p * PITCH + lane + 32], sLo[p * PITCH + lane + 32]);
                float se = v0.x + v1.x, so = v0.y + v1.y;
                #pragma unroll
                for (int off = 16; off; off >>= 1) {
                    se += __shfl_xor_sync(0xFFFFFFFFu, se, off);
                    so += __shfl_xor_sync(0xFFFFFFFFu, so, off);
                }
                if (lane == 0) { sSvF[2 * p] = se; sSvF[2 * p + 1] = so; }
            }
            __syncthreads();
        }

        // ---- build Sv A-tile rows 0 (hi) / 1 (lo) ----
        if (tid < 128) {
            float2 sv = *reinterpret_cast<const float2*>(sSvF + 2 * tid);
            uint2 pa = split2(sv.x, sv.y);
            sSvA[tid * SVP + 0] = pa.x;    // row 0: hi
            sSvA[tid * SVP + 1] = pa.y;    // row 1: lo
        }
        __syncthreads();

        // ---- Tv via MMA: Tv = b1 + (Sv_hi + Sv_lo) @ (inv*W1b) ----
        {
            float accT[2][4];
            #pragma unroll
            for (int jl = 0; jl < 2; ++jl)
                #pragma unroll
                for (int q = 0; q < 4; ++q) accT[jl][q] = 0.f;
            const int u0 = wn * 4 + wm * 2;
            // lane-contiguous: pair index = wm for this warp
            const uint4* bq = reinterpret_cast<const uint4*>(gPk2[3])
                              + wn * 64 + wm * 32 + lane;
            #pragma unroll 4
            for (int s = 0; s < 16; ++s) {
                uint4 q = __ldg(bq + s * 512);
                const int kp0 = (s * 8 + t) * SVP;
                uint32_t ah[4];
                ah[0] = sSvA[kp0 + g];           ah[1] = 0u;   // rows 8-15 zero
                ah[2] = sSvA[kp0 + 4 * SVP + g]; ah[3] = 0u;
                MMA(accT[0], ah, q.x, q.y);
                MMA(accT[1], ah, q.z, q.w);
            }
            #pragma unroll
            for (int jl = 0; jl < 2; ++jl) {
                int n0 = (u0 + jl) * 8 + 2 * t;
                float d0 = accT[jl][0], d1 = accT[jl][1];
                float r0 = __shfl_down_sync(0xFFFFFFFFu, d0, 4);   // row 1 (lo)
                float r1 = __shfl_down_sync(0xFFFFFFFFu, d1, 4);
                if (g == 0) {
                    float2 bb = *reinterpret_cast<const float2*>(b1 + n0);
                    reinterpret_cast<float2*>(sTv)[n0 >> 1] =
                        make_float2(d0 + r0 + bb.x, d1 + r1 + bb.y);
                }
            }
        }

        // ---- GEMM1 ----
        float acc[2][4][4];
        if (step == 0) {
            #pragma unroll
            for (int mt = 0; mt < 2; ++mt)
                #pragma unroll
                for (int jn = 0; jn < 4; ++jn)
                    #pragma unroll
                    for (int q = 0; q < 4; ++q) acc[mt][jn][q] = 0.f;
            gemm_pass(gPk2[1], acc, sHi, wm, wn, lane, g, t);       // G0 = h0@W1c
            #pragma unroll
            for (int mt = 0; mt < 2; ++mt)
                #pragma unroll
                for (int jn = 0; jn < 4; ++jn)
                    gp4[(mt * 4 + jn) * 512] = make_float4(acc[mt][jn][0], acc[mt][jn][1],
                                                           acc[mt][jn][2], acc[mt][jn][3]);
        } else {
            #pragma unroll
            for (int mt = 0; mt < 2; ++mt)
                #pragma unroll
                for (int jn = 0; jn < 4; ++jn) {
                    float4 v = gp4[(mt * 4 + jn) * 512];
                    acc[mt][jn][0] = v.x; acc[mt][jn][1] = v.y;
                    acc[mt][jn][2] = v.z; acc[mt][jn][3] = v.w;
                }
        }
        gemm_pass(gPk2[0], acc, sHi, wm, wn, lane, g, t);           // += h@W1eff
        __syncthreads();

        // ---- epilogue1: act = relu(acc+Tv) -> s* ; acc = h_old + b2 ----
        if (tid < 128)     // zero raw-Sv accumulator for the NEXT step
            reinterpret_cast<float2*>(sSvF)[tid] = make_float2(0.f, 0.f);
        #pragma unroll
        for (int mt = 0; mt < 2; ++mt) {
            const int m0 = wm * 32 + mt * 16 + g;
            #pragma unroll
            for (int jn = 0; jn < 4; ++jn) {
                const int pair = 16 * wn + 4 * jn + t;
                const int n0   = 32 * wn + 8 * jn + 2 * t;
                const int i0 = pair * PITCH + m0;
                float2 hoa = unsplit(sHi[i0],     sLo[i0]);
                float2 hob = unsplit(sHi[i0 + 8], sLo[i0 + 8]);
                float2 tv = *reinterpret_cast<const float2*>(sTv + n0);
                float a0 = fmaxf(acc[mt][jn][0] + tv.x, 0.f);
                float a1 = fmaxf(acc[mt][jn][1] + tv.y, 0.f);
                float a2 = fmaxf(acc[mt][jn][2] + tv.x, 0.f);
                float a3 = fmaxf(acc[mt][jn][3] + tv.y, 0.f);
                uint2 pa = split2(a0, a1);
                uint2 pb = split2(a2, a3);
                sHi[i0] = pa.x;     sLo[i0] = pa.y;
                sHi[i0 + 8] = pb.x; sLo[i0 + 8] = pb.y;
                float2 bb = *reinterpret_cast<const float2*>(b2 + n0);
                acc[mt][jn][0] = hoa.x + bb.x; acc[mt][jn][1] = hoa.y + bb.y;
                acc[mt][jn][2] = hob.x + bb.x; acc[mt][jn][3] = hob.y + bb.y;
            }
        }
        __syncthreads();

        // ---- GEMM2: acc += act @ W2   (acc = new h) ----
        gemm_pass(gPk2[2], acc, sHi, wm, wn, lane, g, t);
        __syncthreads();

        // ---- epilogue2: split new h -> s*; accumulate next Sv ----
        #pragma unroll
        for (int mt = 0; mt < 2; ++mt) {
            const int m0 = wm * 32 + mt * 16 + g;
            #pragma unroll
            for (int jn = 0; jn < 4; ++jn) {
                const int i0 = (16 * wn + 4 * jn + t) * PITCH + m0;
                uint2 pa = split2(acc[mt][jn][0], acc[mt][jn][1]);
                uint2 pb = split2(acc[mt][jn][2], acc[mt][jn][3]);
                sHi[i0] = pa.x;     sLo[i0] = pa.y;
                sHi[i0 + 8] = pb.x; sLo[i0 + 8] = pb.y;
            }
        }
        #pragma unroll
        for (int jn = 0; jn < 4; ++jn) {
            float s0 = acc[0][jn][0] + acc[0][jn][2] + acc[1][jn][0] + acc[1][jn][2];
            float s1 = acc[0][jn][1] + acc[0][jn][3] + acc[1][jn][1] + acc[1][jn][3];
            #pragma unroll
            for (int off = 4; off <= 16; off <<= 1) {      // sum over g (lane bits 2-4)
                s0 += __shfl_xor_sync(0xFFFFFFFFu, s0, off);
                s1 += __shfl_xor_sync(0xFFFFFFFFu, s1, off);
            }
            if (g == 0) {
                int n0 = 32 * wn + 8 * jn + 2 * t;
                atomicAdd(&sSvF[n0],     s0);
                atomicAdd(&sSvF[n0 + 1], s1);
            }
        }
    }

    __syncthreads();
    // ---- logits via MMA on warps wn==0: out = h @ Wd + bd  (hi+lo terms) ----
    if (wn == 0) {
        float accL[2][2][4];
        #pragma unroll
        for (int mt = 0; mt < 2; ++mt)
            #pragma unroll
            for (int jl = 0; jl < 2; ++jl) {
                int n0 = 8 * jl + 2 * t;
                float2 bv = *reinterpret_cast<const float2*>(bd + n0);
                accL[mt][jl][0] = bv.x; accL[mt][jl][1] = bv.y;
                accL[mt][jl][2] = bv.x; accL[mt][jl][3] = bv.y;
            }
        const int mbase = wm * 32 + g;
        const uint4* wq = reinterpret_cast<const uint4*>(gWdPk) + lane;
        #pragma unroll 4
        for (int s = 0; s < 16; ++s) {
            uint4 q = __ldg(wq + s * 32);      // {u=0 frag, u=1 frag}
            const int kp0 = (s * 8 + t) * PITCH + mbase;
            const int kp2 = kp0 + 4 * PITCH;
            #pragma unroll
            for (int mt = 0; mt < 2; ++mt) {
                const int m0 = mt * 16;
                uint32_t ah[4], al[4];
                ah[0] = sHi[kp0 + m0]; ah[1] = sHi[kp0 + m0 + 8];
                ah[2] = sHi[kp2 + m0]; ah[3] = sHi[kp2 + m0 + 8];
                al[0] = sLo[kp0 + m0]; al[1] = sLo[kp0 + m0 + 8];
                al[2] = sLo[kp2 + m0]; al[3] = sLo[kp2 + m0 + 8];
                MMA(accL[mt][0], ah, q.x, q.y);
                MMA(accL[mt][0], al, q.x, q.y);
                MMA(accL[mt][1], ah, q.z, q.w);
                MMA(accL[mt][1], al, q.z, q.w);
            }
        }
        #pragma unroll
        for (int mt = 0; mt < 2; ++mt) {
            const int m0 = wm * 32 + mt * 16 + g;
            #pragma unroll
            for (int jl = 0; jl < 2; ++jl) {
                const int n0 = 8 * jl + 2 * t;
                *reinterpret_cast<float2*>(out + (cta * MAG + m0) * 16 + n0) =
                    make_float2(accL[mt][jl][0], accL[mt][jl][1]);
                *reinterpret_cast<float2*>(out + (cta * MAG + m0 + 8) * 16 + n0) =
                    make_float2(accL[mt][jl][2], accL[mt][jl][3]);
            }
        }
    }
}

extern "C" void kernel_launch(void* const* d_in, const int* in_sizes, int n_in,
                              void* d_out, int out_size)
{
    const int*   ids = (const int*)  d_in[0];
    const float* emb = (const float*)d_in[1];
    const float* W1  = (const float*)d_in[2];
    const float* b1  = (const float*)d_in[3];
    const float* W2  = (const float*)d_in[4];
    const float* b2  = (const float*)d_in[5];
    const float* Wd  = (const float*)d_in[6];
    const float* bd  = (const float*)d_in[7];
    float* out = (float*)d_out;

    const int nCTA = in_sizes[0] / MAG;       // 1024

    prep_all<<<257, 256>>>(W1, W2, Wd);

    cudaFuncSetAttribute(commnet_mma_kernel,
                         cudaFuncAttributeMaxDynamicSharedMemorySize, SMEM_BYTES);
    commnet_mma_kernel<<<nCTA, 512, SMEM_BYTES>>>(ids, b1, b2, bd, emb, out);
}

// round 16
// speedup vs baseline: 1.2440x; 1.0474x over previous
#include <cuda_runtime.h>
#include <cuda_fp16.h>
#include <cstdint>

// ============================================================================
// CommNet via mma.sync m16n8k16 fp16 (compute_100-safe).
// 1 batch per CTA (M=64), grid=1024, 512 threads = 16 warps tiled 2(m) x 8(n).
// 2 CTAs/SM. Round-15/16: h relaid ROW-MAJOR [m][kword] (pitch 132 words) so
// the A operand loads via ldmatrix.m8n8.x4 (1 instr = 4 fragments, was 8 LDS).
// MMAs consume hi split only; lo kept for exact state/Sv/logits.
// B packs lane-contiguous uint4 (round 14). Tv via MMA; Sv incremental.
// G0 = h0 @ W1c computed once (step 0), parked in gmem, re-added steps 1-3.
// ============================================================================

#define HID    256
#define MAG    64
#define STEPS  4
#define INVF   (1.0f/63.0f)
#define HP     132             // uint32 pitch of sHi/sLo rows [m][kword]
#define SVP    24              // uint32 pitch of sSvA[kpair][row]

// SMEM byte offsets
#define SHI_OFF   0            // 64*132*4 = 33792
#define SLO_OFF   33792
#define SSVA_OFF  67584        // 128*24*4 = 12288 (Sv A-tile, rows 0/1 live)
#define SSVF_OFF  79872        // float[256] raw Sv accumulator
#define STV_OFF   80896        // float[256] Tv
#define SMEM_BYTES 81920

// ---------------- device scratch ----------------
// B-frag pack, uint2 units; uint4 slot layout: (s*8+wn)*64 + (jn>>1)*32 + lane.
// g: 0=W1eff 1=W1c 2=W2 3=inv*W1b
__device__ uint2 gPk2[4][16384];
__device__ uint2 gWdPk[1024];               // Wd^T: uint4 slot s*32+lane = {u0,u1}
__device__ float gG0[1024 * 32 * 512];      // [cta][slotgrp4][tid] float4-able

// ---------------- fp16 split helpers ----------------
__device__ __forceinline__ uint2 split2(float x0, float x1) {
    __half2 h = __float22half2_rn(make_float2(x0, x1));    // .x=low=x0
    float2 hf = __half22float2(h);
    __half2 l = __float22half2_rn(make_float2(x0 - hf.x, x1 - hf.y));
    uint2 r;
    r.x = *reinterpret_cast<uint32_t*>(&h);
    r.y = *reinterpret_cast<uint32_t*>(&l);
    return r;
}
__device__ __forceinline__ uint32_t f16x2_single(float x0, float x1) {
    __half2 h = __float22half2_rn(make_float2(x0, x1));
    return *reinterpret_cast<uint32_t*>(&h);
}
__device__ __forceinline__ float2 unsplit(uint32_t hx, uint32_t lx) {
    float2 fh = __half22float2(*reinterpret_cast<__half2*>(&hx));
    float2 fl = __half22float2(*reinterpret_cast<__half2*>(&lx));
    return make_float2(fh.x + fl.x, fh.y + fl.y);
}
__device__ __forceinline__ uint32_t smem_u32(const void* p) {
    uint32_t a;
    asm("{ .reg .u64 t; cvta.to.shared.u64 t, %1; cvt.u32.u64 %0, t; }" : "=r"(a) : "l"(p));
    return a;
}

#define MMA(c, a, B0, B1)                                                      \
    asm volatile("mma.sync.aligned.m16n8k16.row.col.f32.f16.f16.f32 "          \
                 "{%0,%1,%2,%3},{%4,%5,%6,%7},{%8,%9},{%0,%1,%2,%3};"          \
                 : "+f"((c)[0]), "+f"((c)[1]), "+f"((c)[2]), "+f"((c)[3])      \
                 : "r"((a)[0]), "r"((a)[1]), "r"((a)[2]), "r"((a)[3]),         \
                   "r"(B0), "r"(B1));

#define LDSM4(r0, r1, r2, r3, addr)                                            \
    asm volatile("ldmatrix.sync.aligned.m8n8.x4.shared.b16 {%0,%1,%2,%3}, [%4];" \
                 : "=r"(r0), "=r"(r1), "=r"(r2), "=r"(r3) : "r"(addr));

// ---------------- prep kernel (unchanged from round 14) ----------------
__global__ void prep_all(const float* __restrict__ W1, const float* __restrict__ W2,
                         const float* __restrict__ Wd) {
    int bid = blockIdx.x;
    if (bid < 256) {
        int idx = bid * 256 + threadIdx.x;     // 4 * 16384
        int gm = idx >> 14;
        int r  = idx & 16383;
        int s  = r >> 10;
        int u  = (r >> 5) & 31;
        int l  = r & 31;
        int g  = l >> 2, t = l & 3;
        int n  = u * 8 + g;
        int kb = s * 16 + 2 * t;
        int ks[4] = { kb, kb + 1, kb + 8, kb + 9 };
        float v[4];
        #pragma unroll
        for (int q = 0; q < 4; ++q) {
            int k = ks[q];
            if (gm == 0)      v[q] = W1[k * HID + n] - INVF * W1[(HID + k) * HID + n];
            else if (gm == 1) v[q] = W1[(2 * HID + k) * HID + n];
            else if (gm == 2) v[q] = W2[k * HID + n];
            else              v[q] = INVF * W1[(HID + k) * HID + n];
        }
        int wn_ = u >> 2, jn_ = u & 3;
        int nidx = (((s * 8 + wn_) * 64 + (jn_ >> 1) * 32 + l) << 1) + (jn_ & 1);
        gPk2[gm][nidx] = make_uint2(f16x2_single(v[0], v[1]), f16x2_single(v[2], v[3]));
    } else if (bid == 256) {
        for (int e = threadIdx.x; e < 1024; e += 256) {
            int l = e & 31;
            int u = (e >> 5) & 1;
            int s = e >> 6;
            int g = l >> 2, t = l & 3;
            int n = u * 8 + g;
            int kb = s * 16 + 2 * t;
            int ks[4] = { kb, kb + 1, kb + 8, kb + 9 };
            float v[4];
            #pragma unroll
            for (int q = 0; q < 4; ++q) v[q] = Wd[ks[q] * 16 + n];
            gWdPk[s * 64 + l * 2 + u] =
                make_uint2(f16x2_single(v[0], v[1]), f16x2_single(v[2], v[3]));
        }
    }
}

// ---------------- GEMM pass: acc += Ahi @ B  (ldmatrix A) -------------------
__device__ __forceinline__ void gemm_pass(const uint2* __restrict__ bp,
                                          float (&acc)[2][4][4],
                                          uint32_t aB0, uint32_t aB1,
                                          int wn, int lane) {
    const uint4* bq = reinterpret_cast<const uint4*>(bp) + wn * 64 + lane;
    #pragma unroll 2
    for (int s = 0; s < 16; ++s) {
        uint4 q0 = __ldg(bq + s * 512);        // jn 0,1 (coalesced 512B)
        uint4 q1 = __ldg(bq + s * 512 + 32);   // jn 2,3 (coalesced 512B)
        #pragma unroll
        for (int mt = 0; mt < 2; ++mt) {
            uint32_t ah[4];
            LDSM4(ah[0], ah[1], ah[2], ah[3], (mt ? aB1 : aB0) + s * 32);
            MMA(acc[mt][0], ah, q0.x, q0.y);
            MMA(acc[mt][1], ah, q0.z, q0.w);
            MMA(acc[mt][2], ah, q1.x, q1.y);
            MMA(acc[mt][3], ah, q1.z, q1.w);
        }
    }
}

// ---------------- main kernel ----------------
__global__ void __launch_bounds__(512, 2) commnet_mma_kernel(
    const int*   __restrict__ ids,
    const float* __restrict__ b1,
    const float* __restrict__ b2,
    const float* __restrict__ bd,
    const float* __restrict__ emb,
    float*       __restrict__ out)
{
    extern __shared__ uint8_t smraw[];
    uint32_t* sHi  = reinterpret_cast<uint32_t*>(smraw + SHI_OFF);   // [64][132]
    uint32_t* sLo  = reinterpret_cast<uint32_t*>(smraw + SLO_OFF);   // [64][132]
    uint32_t* sSvA = reinterpret_cast<uint32_t*>(smraw + SSVA_OFF);  // [128][24]
    float*    sSvF = reinterpret_cast<float*>(smraw + SSVF_OFF);     // [256]
    float*    sTv  = reinterpret_cast<float*>(smraw + STV_OFF);      // [256]

    const int cta  = blockIdx.x;
    const int tid  = threadIdx.x;
    const int w    = tid >> 5;
    const int lane = tid & 31;
    const int g    = lane >> 2;
    const int t    = lane & 3;
    const int wm   = w >> 3;              // m-half: rows [32wm, 32wm+32)
    const int wn   = w & 7;               // n-slice of 32

    // ldmatrix per-lane base addresses (hi array), mt = 0 / 1
    const uint32_t shiB = smem_u32(smraw + SHI_OFF);
    const int lrow = (lane & 7) + ((lane >> 3) & 1) * 8;   // row within m16 tile
    const int kwo  = (lane >> 4) * 4;                      // k-half word offset
    const uint32_t aB0 = shiB + (uint32_t)(((wm * 32 + lrow) * HP + kwo) << 2);
    const uint32_t aB1 = aB0 + (uint32_t)((16 * HP) << 2);

    // ---- zero Sv A-tile (rows 2-15 stay zero forever) ----
    for (int i = tid; i < 128 * SVP; i += 512) sSvA[i] = 0u;

    // ---- gather: h0 -> row-major split arrays (4x STS.128 each) ----
    {
        int r  = tid >> 3;            // row 0..63
        int qt = tid & 7;             // 16-kword chunk
        int aid = ids[cta * MAG + r];
        const float4* er = reinterpret_cast<const float4*>(emb + aid * HID) + qt * 8;
        uint32_t hw[16], lw[16];
        #pragma unroll
        for (int q = 0; q < 8; ++q) {
            float4 e = er[q];
            uint2 pa = split2(e.x, e.y);
            uint2 pb = split2(e.z, e.w);
            hw[2 * q] = pa.x; hw[2 * q + 1] = pb.x;
            lw[2 * q] = pa.y; lw[2 * q + 1] = pb.y;
        }
        uint4* dh = reinterpret_cast<uint4*>(sHi + r * HP + qt * 16);
        uint4* dl = reinterpret_cast<uint4*>(sLo + r * HP + qt * 16);
        #pragma unroll
        for (int i = 0; i < 4; ++i) {
            dh[i] = make_uint4(hw[4 * i], hw[4 * i + 1], hw[4 * i + 2], hw[4 * i + 3]);
            dl[i] = make_uint4(lw[4 * i], lw[4 * i + 1], lw[4 * i + 2], lw[4 * i + 3]);
        }
    }

    float4* gp4 = reinterpret_cast<float4*>(gG0) + (size_t)cta * 4096 + tid;

    for (int step = 0; step < STEPS; ++step) {
        __syncthreads();

        if (step == 0) {
            // ---- initial Sv (column read; one-time, conflicts acceptable) ----
            #pragma unroll
            for (int pi = 0; pi < 8; ++pi) {
                int p = w * 8 + pi;
                float2 v0 = unsplit(sHi[lane * HP + p],        sLo[lane * HP + p]);
                float2 v1 = unsplit(sHi[(lane + 32) * HP + p], sLo[(lane + 32) * HP + p]);
                float se = v0.x + v1.x, so = v0.y + v1.y;
                #pragma unroll
                for (int off = 16; off; off >>= 1) {
                    se += __shfl_xor_sync(0xFFFFFFFFu, se, off);
                    so += __shfl_xor_sync(0xFFFFFFFFu, so, off);
                }
                if (lane == 0) { sSvF[2 * p] = se; sSvF[2 * p + 1] = so; }
            }
            __syncthreads();
        }

        // ---- build Sv A-tile rows 0 (hi) / 1 (lo) ----
        if (tid < 128) {
            float2 sv = *reinterpret_cast<const float2*>(sSvF + 2 * tid);
            uint2 pa = split2(sv.x, sv.y);
            sSvA[tid * SVP + 0] = pa.x;    // row 0: hi
            sSvA[tid * SVP + 1] = pa.y;    // row 1: lo
        }
        __syncthreads();

        // ---- Tv via MMA: Tv = b1 + (Sv_hi + Sv_lo) @ (inv*W1b) ----
        {
            float accT[2][4];
            #pragma unroll
            for (int jl = 0; jl < 2; ++jl)
                #pragma unroll
                for (int q = 0; q < 4; ++q) accT[jl][q] = 0.f;
            const int u0 = wn * 4 + wm * 2;
            const uint4* bq = reinterpret_cast<const uint4*>(gPk2[3])
                              + wn * 64 + wm * 32 + lane;
            #pragma unroll 4
            for (int s = 0; s < 16; ++s) {
                uint4 q = __ldg(bq + s * 512);
                const int kp0 = (s * 8 + t) * SVP;
                uint32_t ah[4];
                ah[0] = sSvA[kp0 + g];           ah[1] = 0u;   // rows 8-15 zero
                ah[2] = sSvA[kp0 + 4 * SVP + g]; ah[3] = 0u;
                MMA(accT[0], ah, q.x, q.y);
                MMA(accT[1], ah, q.z, q.w);
            }
            #pragma unroll
            for (int jl = 0; jl < 2; ++jl) {
                int n0 = (u0 + jl) * 8 + 2 * t;
                float d0 = accT[jl][0], d1 = accT[jl][1];
                float r0 = __shfl_down_sync(0xFFFFFFFFu, d0, 4);   // row 1 (lo)
                float r1 = __shfl_down_sync(0xFFFFFFFFu, d1, 4);
                if (g == 0) {
                    float2 bb = *reinterpret_cast<const float2*>(b1 + n0);
                    reinterpret_cast<float2*>(sTv)[n0 >> 1] =
                        make_float2(d0 + r0 + bb.x, d1 + r1 + bb.y);
                }
            }
        }

        // ---- GEMM1 ----
        float acc[2][4][4];
        if (step == 0) {
            #pragma unroll
            for (int mt = 0; mt < 2; ++mt)
                #pragma unroll
                for (int jn = 0; jn < 4; ++jn)
                    #pragma unroll
                    for (int q = 0; q < 4; ++q) acc[mt][jn][q] = 0.f;
            gemm_pass(gPk2[1], acc, aB0, aB1, wn, lane);            // G0 = h0@W1c
            #pragma unroll
            for (int mt = 0; mt < 2; ++mt)
                #pragma unroll
                for (int jn = 0; jn < 4; ++jn)
                    gp4[(mt * 4 + jn) * 512] = make_float4(acc[mt][jn][0], acc[mt][jn][1],
                                                           acc[mt][jn][2], acc[mt][jn][3]);
        } else {
            #pragma unroll
            for (int mt = 0; mt < 2; ++mt)
                #pragma unroll
                for (int jn = 0; jn < 4; ++jn) {
                    float4 v = gp4[(mt * 4 + jn) * 512];
                    acc[mt][jn][0] = v.x; acc[mt][jn][1] = v.y;
                    acc[mt][jn][2] = v.z; acc[mt][jn][3] = v.w;
                }
        }
        gemm_pass(gPk2[0], acc, aB0, aB1, wn, lane);                // += h@W1eff
        __syncthreads();

        // ---- epilogue1: act = relu(acc+Tv) -> s* ; acc = h_old + b2 ----
        if (tid < 128)     // zero raw-Sv accumulator for the NEXT step
            reinterpret_cast<float2*>(sSvF)[tid] = make_float2(0.f, 0.f);
        #pragma unroll
        for (int mt = 0; mt < 2; ++mt) {
            const int m0 = wm * 32 + mt * 16 + g;
            #pragma unroll
            for (int jn = 0; jn < 4; ++jn) {
                const int pair = 16 * wn + 4 * jn + t;
                const int n0   = 32 * wn + 8 * jn + 2 * t;
                const int i0 = m0 * HP + pair;          // row m0
                const int i1 = (m0 + 8) * HP + pair;    // row m0+8
                float2 hoa = unsplit(sHi[i0], sLo[i0]);
                float2 hob = unsplit(sHi[i1], sLo[i1]);
                float2 tv = *reinterpret_cast<const float2*>(sTv + n0);
                float a0 = fmaxf(acc[mt][jn][0] + tv.x, 0.f);
                float a1 = fmaxf(acc[mt][jn][1] + tv.y, 0.f);
                float a2 = fmaxf(acc[mt][jn][2] + tv.x, 0.f);
                float a3 = fmaxf(acc[mt][jn][3] + tv.y, 0.f);
                uint2 pa = split2(a0, a1);
                uint2 pb = split2(a2, a3);
                sHi[i0] = pa.x; sLo[i0] = pa.y;
                sHi[i1] = pb.x; sLo[i1] = pb.y;
                float2 bb = *reinterpret_cast<const float2*>(b2 + n0);
                acc[mt][jn][0] = hoa.x + bb.x; acc[mt][jn][1] = hoa.y + bb.y;
                acc[mt][jn][2] = hob.x + bb.x; acc[mt][jn][3] = hob.y + bb.y;
            }
        }
        __syncthreads();

        // ---- GEMM2: acc += act @ W2   (acc = new h) ----
        gemm_pass(gPk2[2], acc, aB0, aB1, wn, lane);
        __syncthreads();

        // ---- epilogue2: split new h -> s*; accumulate next Sv ----
        #pragma unroll
        for (int mt = 0; mt < 2; ++mt) {
            const int m0 = wm * 32 + mt * 16 + g;
            #pragma unroll
            for (int jn = 0; jn < 4; ++jn) {
                const int pair = 16 * wn + 4 * jn + t;
                const int i0 = m0 * HP + pair;
                const int i1 = (m0 + 8) * HP + pair;
                uint2 pa = split2(acc[mt][jn][0], acc[mt][jn][1]);
                uint2 pb = split2(acc[mt][jn][2], acc[mt][jn][3]);
                sHi[i0] = pa.x; sLo[i0] = pa.y;
                sHi[i1] = pb.x; sLo[i1] = pb.y;
            }
        }
        #pragma unroll
        for (int jn = 0; jn < 4; ++jn) {
            float s0 = acc[0][jn][0] + acc[0][jn][2] + acc[1][jn][0] + acc[1][jn][2];
            float s1 = acc[0][jn][1] + acc[0][jn][3] + acc[1][jn][1] + acc[1][jn][3];
            #pragma unroll
            for (int off = 4; off <= 16; off <<= 1) {      // sum over g (lane bits 2-4)
                s0 += __shfl_xor_sync(0xFFFFFFFFu, s0, off);
                s1 += __shfl_xor_sync(0xFFFFFFFFu, s1, off);
            }
            if (g == 0) {
                int n0 = 32 * wn + 8 * jn + 2 * t;
                atomicAdd(&sSvF[n0],     s0);
                atomicAdd(&sSvF[n0 + 1], s1);
            }
        }
    }

    __syncthreads();
    // ---- logits via MMA on warps wn==0: out = h @ Wd + bd  (hi+lo terms) ----
    if (wn == 0) {
        float accL[2][2][4];
        #pragma unroll
        for (int mt = 0; mt < 2; ++mt)
            #pragma unroll
            for (int jl = 0; jl < 2; ++jl) {
                int n0 = 8 * jl + 2 * t;
                float2 bv = *reinterpret_cast<const float2*>(bd + n0);
                accL[mt][jl][0] = bv.x; accL[mt][jl][1] = bv.y;
                accL[mt][jl][2] = bv.x; accL[mt][jl][3] = bv.y;
            }
        const uint32_t loOfs = (uint32_t)(SLO_OFF - SHI_OFF);
        const uint4* wq = reinterpret_cast<const uint4*>(gWdPk) + lane;
        #pragma unroll 4
        for (int s = 0; s < 16; ++s) {
            uint4 q = __ldg(wq + s * 32);      // {u=0 frag, u=1 frag}
            #pragma unroll
            for (int mt = 0; mt < 2; ++mt) {
                uint32_t base = (mt ? aB1 : aB0) + s * 32;
                uint32_t ah[4], al[4];
                LDSM4(ah[0], ah[1], ah[2], ah[3], base);
                LDSM4(al[0], al[1], al[2], al[3], base + loOfs);
                MMA(accL[mt][0], ah, q.x, q.y);
                MMA(accL[mt][0], al, q.x, q.y);
                MMA(accL[mt][1], ah, q.z, q.w);
                MMA(accL[mt][1], al, q.z, q.w);
            }
        }
        #pragma unroll
        for (int mt = 0; mt < 2; ++mt) {
            const int m0 = wm * 32 + mt * 16 + g;
            #pragma unroll
            for (int jl = 0; jl < 2; ++jl) {
                const int n0 = 8 * jl + 2 * t;
                *reinterpret_cast<float2*>(out + (cta * MAG + m0) * 16 + n0) =
                    make_float2(accL[mt][jl][0], accL[mt][jl][1]);
                *reinterpret_cast<float2*>(out + (cta * MAG + m0 + 8) * 16 + n0) =
                    make_float2(accL[mt][jl][2], accL[mt][jl][3]);
            }
        }
    }
}

extern "C" void kernel_launch(void* const* d_in, const int* in_sizes, int n_in,
                              void* d_out, int out_size)
{
    const int*   ids = (const int*)  d_in[0];
    const float* emb = (const float*)d_in[1];
    const float* W1  = (const float*)d_in[2];
    const float* b1  = (const float*)d_in[3];
    const float* W2  = (const float*)d_in[4];
    const float* b2  = (const float*)d_in[5];
    const float* Wd  = (const float*)d_in[6];
    const float* bd  = (const float*)d_in[7];
    float* out = (float*)d_out;

    const int nCTA = in_sizes[0] / MAG;       // 1024

    prep_all<<<257, 256>>>(W1, W2, Wd);

    cudaFuncSetAttribute(commnet_mma_kernel,
                         cudaFuncAttributeMaxDynamicSharedMemorySize, SMEM_BYTES);
    commnet_mma_kernel<<<nCTA, 512, SMEM_BYTES>>>(ids, b1, b2, bd, emb, out);
}

// round 17
// speedup vs baseline: 1.2912x; 1.0380x over previous
#include <cuda_runtime.h>
#include <cuda_fp16.h>
#include <cstdint>

// ============================================================================
// CommNet via mma.sync m16n8k16 fp16 (compute_100-safe).
// 1 batch per CTA (M=64), grid=1024, 512 threads = 16 warps tiled 2(m) x 8(n).
// 2 CTAs/SM. h ROW-MAJOR [m][kword] (pitch 132) -> A via ldmatrix.m8n8.x4.
// MMAs consume hi split only; lo kept for exact state/Sv/logits.
// Round-17: ep1's act-lo split was DEAD (GEMM2 reads sHi only; sLo's next
// readers see h-lo from ep2) -> removed its cvt chain + 16 STS.32/thread/step.
// Bit-exact vs round 16.
// B packs lane-contiguous uint4. Tv via MMA; Sv incremental.
// G0 = h0 @ W1c computed once (step 0), parked in gmem, re-added steps 1-3.
// ============================================================================

#define HID    256
#define MAG    64
#define STEPS  4
#define INVF   (1.0f/63.0f)
#define HP     132             // uint32 pitch of sHi/sLo rows [m][kword]
#define SVP    24              // uint32 pitch of sSvA[kpair][row]

// SMEM byte offsets
#define SHI_OFF   0            // 64*132*4 = 33792
#define SLO_OFF   33792
#define SSVA_OFF  67584        // 128*24*4 = 12288 (Sv A-tile, rows 0/1 live)
#define SSVF_OFF  79872        // float[256] raw Sv accumulator
#define STV_OFF   80896        // float[256] Tv
#define SMEM_BYTES 81920

// ---------------- device scratch ----------------
// B-frag pack, uint2 units; uint4 slot layout: (s*8+wn)*64 + (jn>>1)*32 + lane.
// g: 0=W1eff 1=W1c 2=W2 3=inv*W1b
__device__ uint2 gPk2[4][16384];
__device__ uint2 gWdPk[1024];               // Wd^T: uint4 slot s*32+lane = {u0,u1}
__device__ float gG0[1024 * 32 * 512];      // [cta][slotgrp4][tid] float4-able

// ---------------- fp16 split helpers ----------------
__device__ __forceinline__ uint2 split2(float x0, float x1) {
    __half2 h = __float22half2_rn(make_float2(x0, x1));    // .x=low=x0
    float2 hf = __half22float2(h);
    __half2 l = __float22half2_rn(make_float2(x0 - hf.x, x1 - hf.y));
    uint2 r;
    r.x = *reinterpret_cast<uint32_t*>(&h);
    r.y = *reinterpret_cast<uint32_t*>(&l);
    return r;
}
__device__ __forceinline__ uint32_t f16x2_single(float x0, float x1) {
    __half2 h = __float22half2_rn(make_float2(x0, x1));
    return *reinterpret_cast<uint32_t*>(&h);
}
__device__ __forceinline__ float2 unsplit(uint32_t hx, uint32_t lx) {
    float2 fh = __half22float2(*reinterpret_cast<__half2*>(&hx));
    float2 fl = __half22float2(*reinterpret_cast<__half2*>(&lx));
    return make_float2(fh.x + fl.x, fh.y + fl.y);
}
__device__ __forceinline__ uint32_t smem_u32(const void* p) {
    uint32_t a;
    asm("{ .reg .u64 t; cvta.to.shared.u64 t, %1; cvt.u32.u64 %0, t; }" : "=r"(a) : "l"(p));
    return a;
}

#define MMA(c, a, B0, B1)                                                      \
    asm volatile("mma.sync.aligned.m16n8k16.row.col.f32.f16.f16.f32 "          \
                 "{%0,%1,%2,%3},{%4,%5,%6,%7},{%8,%9},{%0,%1,%2,%3};"          \
                 : "+f"((c)[0]), "+f"((c)[1]), "+f"((c)[2]), "+f"((c)[3])      \
                 : "r"((a)[0]), "r"((a)[1]), "r"((a)[2]), "r"((a)[3]),         \
                   "r"(B0), "r"(B1));

#define LDSM4(r0, r1, r2, r3, addr)                                            \
    asm volatile("ldmatrix.sync.aligned.m8n8.x4.shared.b16 {%0,%1,%2,%3}, [%4];" \
                 : "=r"(r0), "=r"(r1), "=r"(r2), "=r"(r3) : "r"(addr));

// ---------------- prep kernel (unchanged) ----------------
__global__ void prep_all(const float* __restrict__ W1, const float* __restrict__ W2,
                         const float* __restrict__ Wd) {
    int bid = blockIdx.x;
    if (bid < 256) {
        int idx = bid * 256 + threadIdx.x;     // 4 * 16384
        int gm = idx >> 14;
        int r  = idx & 16383;
        int s  = r >> 10;
        int u  = (r >> 5) & 31;
        int l  = r & 31;
        int g  = l >> 2, t = l & 3;
        int n  = u * 8 + g;
        int kb = s * 16 + 2 * t;
        int ks[4] = { kb, kb + 1, kb + 8, kb + 9 };
        float v[4];
        #pragma unroll
        for (int q = 0; q < 4; ++q) {
            int k = ks[q];
            if (gm == 0)      v[q] = W1[k * HID + n] - INVF * W1[(HID + k) * HID + n];
            else if (gm == 1) v[q] = W1[(2 * HID + k) * HID + n];
            else if (gm == 2) v[q] = W2[k * HID + n];
            else              v[q] = INVF * W1[(HID + k) * HID + n];
        }
        int wn_ = u >> 2, jn_ = u & 3;
        int nidx = (((s * 8 + wn_) * 64 + (jn_ >> 1) * 32 + l) << 1) + (jn_ & 1);
        gPk2[gm][nidx] = make_uint2(f16x2_single(v[0], v[1]), f16x2_single(v[2], v[3]));
    } else if (bid == 256) {
        for (int e = threadIdx.x; e < 1024; e += 256) {
            int l = e & 31;
            int u = (e >> 5) & 1;
            int s = e >> 6;
            int g = l >> 2, t = l & 3;
            int n = u * 8 + g;
            int kb = s * 16 + 2 * t;
            int ks[4] = { kb, kb + 1, kb + 8, kb + 9 };
            float v[4];
            #pragma unroll
            for (int q = 0; q < 4; ++q) v[q] = Wd[ks[q] * 16 + n];
            gWdPk[s * 64 + l * 2 + u] =
                make_uint2(f16x2_single(v[0], v[1]), f16x2_single(v[2], v[3]));
        }
    }
}

// ---------------- GEMM pass: acc += Ahi @ B  (ldmatrix A) -------------------
__device__ __forceinline__ void gemm_pass(const uint2* __restrict__ bp,
                                          float (&acc)[2][4][4],
                                          uint32_t aB0, uint32_t aB1,
                                          int wn, int lane) {
    const uint4* bq = reinterpret_cast<const uint4*>(bp) + wn * 64 + lane;
    #pragma unroll 2
    for (int s = 0; s < 16; ++s) {
        uint4 q0 = __ldg(bq + s * 512);        // jn 0,1 (coalesced 512B)
        uint4 q1 = __ldg(bq + s * 512 + 32);   // jn 2,3 (coalesced 512B)
        #pragma unroll
        for (int mt = 0; mt < 2; ++mt) {
            uint32_t ah[4];
            LDSM4(ah[0], ah[1], ah[2], ah[3], (mt ? aB1 : aB0) + s * 32);
            MMA(acc[mt][0], ah, q0.x, q0.y);
            MMA(acc[mt][1], ah, q0.z, q0.w);
            MMA(acc[mt][2], ah, q1.x, q1.y);
            MMA(acc[mt][3], ah, q1.z, q1.w);
        }
    }
}

// ---------------- main kernel ----------------
__global__ void __launch_bounds__(512, 2) commnet_mma_kernel(
    const int*   __restrict__ ids,
    const float* __restrict__ b1,
    const float* __restrict__ b2,
    const float* __restrict__ bd,
    const float* __restrict__ emb,
    float*       __restrict__ out)
{
    extern __shared__ uint8_t smraw[];
    uint32_t* sHi  = reinterpret_cast<uint32_t*>(smraw + SHI_OFF);   // [64][132]
    uint32_t* sLo  = reinterpret_cast<uint32_t*>(smraw + SLO_OFF);   // [64][132]
    uint32_t* sSvA = reinterpret_cast<uint32_t*>(smraw + SSVA_OFF);  // [128][24]
    float*    sSvF = reinterpret_cast<float*>(smraw + SSVF_OFF);     // [256]
    float*    sTv  = reinterpret_cast<float*>(smraw + STV_OFF);      // [256]

    const int cta  = blockIdx.x;
    const int tid  = threadIdx.x;
    const int w    = tid >> 5;
    const int lane = tid & 31;
    const int g    = lane >> 2;
    const int t    = lane & 3;
    const int wm   = w >> 3;              // m-half: rows [32wm, 32wm+32)
    const int wn   = w & 7;               // n-slice of 32

    // ldmatrix per-lane base addresses (hi array), mt = 0 / 1
    const uint32_t shiB = smem_u32(smraw + SHI_OFF);
    const int lrow = (lane & 7) + ((lane >> 3) & 1) * 8;   // row within m16 tile
    const int kwo  = (lane >> 4) * 4;                      // k-half word offset
    const uint32_t aB0 = shiB + (uint32_t)(((wm * 32 + lrow) * HP + kwo) << 2);
    const uint32_t aB1 = aB0 + (uint32_t)((16 * HP) << 2);

    // ---- zero Sv A-tile (rows 2-15 stay zero forever) ----
    for (int i = tid; i < 128 * SVP; i += 512) sSvA[i] = 0u;

    // ---- gather: h0 -> row-major split arrays (4x STS.128 each) ----
    {
        int r  = tid >> 3;            // row 0..63
        int qt = tid & 7;             // 16-kword chunk
        int aid = ids[cta * MAG + r];
        const float4* er = reinterpret_cast<const float4*>(emb + aid * HID) + qt * 8;
        uint32_t hw[16], lw[16];
        #pragma unroll
        for (int q = 0; q < 8; ++q) {
            float4 e = er[q];
            uint2 pa = split2(e.x, e.y);
            uint2 pb = split2(e.z, e.w);
            hw[2 * q] = pa.x; hw[2 * q + 1] = pb.x;
            lw[2 * q] = pa.y; lw[2 * q + 1] = pb.y;
        }
        uint4* dh = reinterpret_cast<uint4*>(sHi + r * HP + qt * 16);
        uint4* dl = reinterpret_cast<uint4*>(sLo + r * HP + qt * 16);
        #pragma unroll
        for (int i = 0; i < 4; ++i) {
            dh[i] = make_uint4(hw[4 * i], hw[4 * i + 1], hw[4 * i + 2], hw[4 * i + 3]);
            dl[i] = make_uint4(lw[4 * i], lw[4 * i + 1], lw[4 * i + 2], lw[4 * i + 3]);
        }
    }

    float4* gp4 = reinterpret_cast<float4*>(gG0) + (size_t)cta * 4096 + tid;

    for (int step = 0; step < STEPS; ++step) {
        __syncthreads();

        if (step == 0) {
            // ---- initial Sv (column read; one-time, conflicts acceptable) ----
            #pragma unroll
            for (int pi = 0; pi < 8; ++pi) {
                int p = w * 8 + pi;
                float2 v0 = unsplit(sHi[lane * HP + p],        sLo[lane * HP + p]);
                float2 v1 = unsplit(sHi[(lane + 32) * HP + p], sLo[(lane + 32) * HP + p]);
                float se = v0.x + v1.x, so = v0.y + v1.y;
                #pragma unroll
                for (int off = 16; off; off >>= 1) {
                    se += __shfl_xor_sync(0xFFFFFFFFu, se, off);
                    so += __shfl_xor_sync(0xFFFFFFFFu, so, off);
                }
                if (lane == 0) { sSvF[2 * p] = se; sSvF[2 * p + 1] = so; }
            }
            __syncthreads();
        }

        // ---- build Sv A-tile rows 0 (hi) / 1 (lo) ----
        if (tid < 128) {
            float2 sv = *reinterpret_cast<const float2*>(sSvF + 2 * tid);
            uint2 pa = split2(sv.x, sv.y);
            sSvA[tid * SVP + 0] = pa.x;    // row 0: hi
            sSvA[tid * SVP + 1] = pa.y;    // row 1: lo
        }
        __syncthreads();

        // ---- Tv via MMA: Tv = b1 + (Sv_hi + Sv_lo) @ (inv*W1b) ----
        {
            float accT[2][4];
            #pragma unroll
            for (int jl = 0; jl < 2; ++jl)
                #pragma unroll
                for (int q = 0; q < 4; ++q) accT[jl][q] = 0.f;
            const int u0 = wn * 4 + wm * 2;
            const uint4* bq = reinterpret_cast<const uint4*>(gPk2[3])
                              + wn * 64 + wm * 32 + lane;
            #pragma unroll 4
            for (int s = 0; s < 16; ++s) {
                uint4 q = __ldg(bq + s * 512);
                const int kp0 = (s * 8 + t) * SVP;
                uint32_t ah[4];
                ah[0] = sSvA[kp0 + g];           ah[1] = 0u;   // rows 8-15 zero
                ah[2] = sSvA[kp0 + 4 * SVP + g]; ah[3] = 0u;
                MMA(accT[0], ah, q.x, q.y);
                MMA(accT[1], ah, q.z, q.w);
            }
            #pragma unroll
            for (int jl = 0; jl < 2; ++jl) {
                int n0 = (u0 + jl) * 8 + 2 * t;
                float d0 = accT[jl][0], d1 = accT[jl][1];
                float r0 = __shfl_down_sync(0xFFFFFFFFu, d0, 4);   // row 1 (lo)
                float r1 = __shfl_down_sync(0xFFFFFFFFu, d1, 4);
                if (g == 0) {
                    float2 bb = *reinterpret_cast<const float2*>(b1 + n0);
                    reinterpret_cast<float2*>(sTv)[n0 >> 1] =
                        make_float2(d0 + r0 + bb.x, d1 + r1 + bb.y);
                }
            }
        }

        // ---- GEMM1 ----
        float acc[2][4][4];
        if (step == 0) {
            #pragma unroll
            for (int mt = 0; mt < 2; ++mt)
                #pragma unroll
                for (int jn = 0; jn < 4; ++jn)
                    #pragma unroll
                    for (int q = 0; q < 4; ++q) acc[mt][jn][q] = 0.f;
            gemm_pass(gPk2[1], acc, aB0, aB1, wn, lane);            // G0 = h0@W1c
            #pragma unroll
            for (int mt = 0; mt < 2; ++mt)
                #pragma unroll
                for (int jn = 0; jn < 4; ++jn)
                    gp4[(mt * 4 + jn) * 512] = make_float4(acc[mt][jn][0], acc[mt][jn][1],
                                                           acc[mt][jn][2], acc[mt][jn][3]);
        } else {
            #pragma unroll
            for (int mt = 0; mt < 2; ++mt)
                #pragma unroll
                for (int jn = 0; jn < 4; ++jn) {
                    float4 v = gp4[(mt * 4 + jn) * 512];
                    acc[mt][jn][0] = v.x; acc[mt][jn][1] = v.y;
                    acc[mt][jn][2] = v.z; acc[mt][jn][3] = v.w;
                }
        }
        gemm_pass(gPk2[0], acc, aB0, aB1, wn, lane);                // += h@W1eff
        __syncthreads();

        // ---- epilogue1: act = relu(acc+Tv) -> sHi ONLY (act-lo is dead);
        //      acc = h_old + b2 ----
        if (tid < 128)     // zero raw-Sv accumulator for the NEXT step
            reinterpret_cast<float2*>(sSvF)[tid] = make_float2(0.f, 0.f);
        #pragma unroll
        for (int mt = 0; mt < 2; ++mt) {
            const int m0 = wm * 32 + mt * 16 + g;
            #pragma unroll
            for (int jn = 0; jn < 4; ++jn) {
                const int pair = 16 * wn + 4 * jn + t;
                const int n0   = 32 * wn + 8 * jn + 2 * t;
                const int i0 = m0 * HP + pair;          // row m0
                const int i1 = (m0 + 8) * HP + pair;    // row m0+8
                float2 hoa = unsplit(sHi[i0], sLo[i0]);
                float2 hob = unsplit(sHi[i1], sLo[i1]);
                float2 tv = *reinterpret_cast<const float2*>(sTv + n0);
                float a0 = fmaxf(acc[mt][jn][0] + tv.x, 0.f);
                float a1 = fmaxf(acc[mt][jn][1] + tv.y, 0.f);
                float a2 = fmaxf(acc[mt][jn][2] + tv.x, 0.f);
                float a3 = fmaxf(acc[mt][jn][3] + tv.y, 0.f);
                sHi[i0] = f16x2_single(a0, a1);         // act hi only
                sHi[i1] = f16x2_single(a2, a3);
                float2 bb = *reinterpret_cast<const float2*>(b2 + n0);
                acc[mt][jn][0] = hoa.x + bb.x; acc[mt][jn][1] = hoa.y + bb.y;
                acc[mt][jn][2] = hob.x + bb.x; acc[mt][jn][3] = hob.y + bb.y;
            }
        }
        __syncthreads();

        // ---- GEMM2: acc += act @ W2   (acc = new h) ----
        gemm_pass(gPk2[2], acc, aB0, aB1, wn, lane);
        __syncthreads();

        // ---- epilogue2: split new h -> s*; accumulate next Sv ----
        #pragma unroll
        for (int mt = 0; mt < 2; ++mt) {
            const int m0 = wm * 32 + mt * 16 + g;
            #pragma unroll
            for (int jn = 0; jn < 4; ++jn) {
                const int pair = 16 * wn + 4 * jn + t;
                const int i0 = m0 * HP + pair;
                const int i1 = (m0 + 8) * HP + pair;
                uint2 pa = split2(acc[mt][jn][0], acc[mt][jn][1]);
                uint2 pb = split2(acc[mt][jn][2], acc[mt][jn][3]);
                sHi[i0] = pa.x; sLo[i0] = pa.y;
                sHi[i1] = pb.x; sLo[i1] = pb.y;
            }
        }
        #pragma unroll
        for (int jn = 0; jn < 4; ++jn) {
            float s0 = acc[0][jn][0] + acc[0][jn][2] + acc[1][jn][0] + acc[1][jn][2];
            float s1 = acc[0][jn][1] + acc[0][jn][3] + acc[1][jn][1] + acc[1][jn][3];
            #pragma unroll
            for (int off = 4; off <= 16; off <<= 1) {      // sum over g (lane bits 2-4)
                s0 += __shfl_xor_sync(0xFFFFFFFFu, s0, off);
                s1 += __shfl_xor_sync(0xFFFFFFFFu, s1, off);
            }
            if (g == 0) {
                int n0 = 32 * wn + 8 * jn + 2 * t;
                atomicAdd(&sSvF[n0],     s0);
                atomicAdd(&sSvF[n0 + 1], s1);
            }
        }
    }

    __syncthreads();
    // ---- logits via MMA on warps wn==0: out = h @ Wd + bd  (hi+lo terms) ----
    if (wn == 0) {
        float accL[2][2][4];
        #pragma unroll
        for (int mt = 0; mt < 2; ++mt)
            #pragma unroll
            for (int jl = 0; jl < 2; ++jl) {
                int n0 = 8 * jl + 2 * t;
                float2 bv = *reinterpret_cast<const float2*>(bd + n0);
                accL[mt][jl][0] = bv.x; accL[mt][jl][1] = bv.y;
                accL[mt][jl][2] = bv.x; accL[mt][jl][3] = bv.y;
            }
        const uint32_t loOfs = (uint32_t)(SLO_OFF - SHI_OFF);
        const uint4* wq = reinterpret_cast<const uint4*>(gWdPk) + lane;
        #pragma unroll 4
        for (int s = 0; s < 16; ++s) {
            uint4 q = __ldg(wq + s * 32);      // {u=0 frag, u=1 frag}
            #pragma unroll
            for (int mt = 0; mt < 2; ++mt) {
                uint32_t base = (mt ? aB1 : aB0) + s * 32;
                uint32_t ah[4], al[4];
                LDSM4(ah[0], ah[1], ah[2], ah[3], base);
                LDSM4(al[0], al[1], al[2], al[3], base + loOfs);
                MMA(accL[mt][0], ah, q.x, q.y);
                MMA(accL[mt][0], al, q.x, q.y);
                MMA(accL[mt][1], ah, q.z, q.w);
                MMA(accL[mt][1], al, q.z, q.w);
            }
        }
        #pragma unroll
        for (int mt = 0; mt < 2; ++mt) {
            const int m0 = wm * 32 + mt * 16 + g;
            #pragma unroll
            for (int jl = 0; jl < 2; ++jl) {
                const int n0 = 8 * jl + 2 * t;
                *reinterpret_cast<float2*>(out + (cta * MAG + m0) * 16 + n0) =
                    make_float2(accL[mt][jl][0], accL[mt][jl][1]);
                *reinterpret_cast<float2*>(out + (cta * MAG + m0 + 8) * 16 + n0) =
                    make_float2(accL[mt][jl][2], accL[mt][jl][3]);
            }
        }
    }
}

extern "C" void kernel_launch(void* const* d_in, const int* in_sizes, int n_in,
                              void* d_out, int out_size)
{
    const int*   ids = (const int*)  d_in[0];
    const float* emb = (const float*)d_in[1];
    const float* W1  = (const float*)d_in[2];
    const float* b1  = (const float*)d_in[3];
    const float* W2  = (const float*)d_in[4];
    const float* b2  = (const float*)d_in[5];
    const float* Wd  = (const float*)d_in[6];
    const float* bd  = (const float*)d_in[7];
    float* out = (float*)d_out;

    const int nCTA = in_sizes[0] / MAG;       // 1024

    prep_all<<<257, 256>>>(W1, W2, Wd);

    cudaFuncSetAttribute(commnet_mma_kernel,
                         cudaFuncAttributeMaxDynamicSharedMemorySize, SMEM_BYTES);
    commnet_mma_kernel<<<nCTA, 512, SMEM_BYTES>>>(ids, b1, b2, bd, emb, out);
}